// round 2
// baseline (speedup 1.0000x reference)
#include <cuda_runtime.h>
#include <cuda_bf16.h>

// Problem constants
#define NNODES 50000
#define NEDGES 800000
#define INDIM  128
#define HID    256
#define NGRAPH 128
#define NCLS   16

// ---------------- device scratch (no cudaMalloc allowed) ----------------
__device__ float g_bufA[NNODES * HID];
__device__ float g_bufB[NNODES * HID];
__device__ float g_dinv[NNODES];
__device__ int   g_indeg[NNODES];
__device__ int   g_row_ptr[NNODES + 1];
__device__ int   g_cursor[NNODES];
__device__ int   g_csr_src[NEDGES];
__device__ int   g_gcnt[NGRAPH];
__device__ int   g_gstart[NGRAPH + 1];
__device__ float g_pool[NGRAPH * HID];
__device__ int   g_is64;   // 1 if indices are int64, 0 if int32

// Read index i from a buffer that is either int32 or int64.
__device__ __forceinline__ int get_idx(const void* p, int i, int is64) {
    if (is64) return (int)((const long long*)p)[i];
    return ((const int*)p)[i];
}

// ---------------- dtype detection ----------------
// If the buffer is int64 (values in [0, 50000)), every odd 32-bit word is 0.
// If int32, odd words are random edge indices — essentially never all zero.
__global__ void detect_dtype_kernel(const int* __restrict__ w, int nOddSamples) {
    __shared__ int found;
    if (threadIdx.x == 0) found = 0;
    __syncthreads();
    for (int i = threadIdx.x; i < nOddSamples; i += blockDim.x) {
        if (w[2 * i + 1] != 0) found = 1;
    }
    __syncthreads();
    if (threadIdx.x == 0) g_is64 = found ? 0 : 1;
}

// ---------------- small utility kernels ----------------
__global__ void zero_int_kernel(int* p, int n) {
    int i = blockIdx.x * blockDim.x + threadIdx.x;
    if (i < n) p[i] = 0;
}

__global__ void hist_dst_kernel(const void* __restrict__ ei, int E, int* __restrict__ indeg) {
    int e = blockIdx.x * blockDim.x + threadIdx.x;
    if (e < E) {
        int d = get_idx(ei, E + e, g_is64);
        atomicAdd(&indeg[d], 1);
    }
}

__global__ void hist_batch_kernel(const void* __restrict__ batch, int n, int* __restrict__ gcnt) {
    int i = blockIdx.x * blockDim.x + threadIdx.x;
    if (i < n) {
        int g = get_idx(batch, i, g_is64);
        atomicAdd(&gcnt[g], 1);
    }
}

__global__ void dinv_kernel(const int* __restrict__ indeg, float* __restrict__ dinv, int n) {
    int i = blockIdx.x * blockDim.x + threadIdx.x;
    if (i < n) dinv[i] = rsqrtf((float)indeg[i] + 1.0f);
}

// exclusive scan over n counts -> row_ptr[0..n], cursor[i] = row_ptr[i]
__global__ void scan_kernel(const int* __restrict__ counts, int* __restrict__ row_ptr,
                            int* __restrict__ cursor, int n) {
    __shared__ int s[1024];
    __shared__ int carry;
    int tid = threadIdx.x;
    if (tid == 0) { carry = 0; row_ptr[0] = 0; }
    __syncthreads();
    for (int base = 0; base < n; base += 1024) {
        int i = base + tid;
        int v = (i < n) ? counts[i] : 0;
        s[tid] = v;
        __syncthreads();
        for (int off = 1; off < 1024; off <<= 1) {
            int t = (tid >= off) ? s[tid - off] : 0;
            __syncthreads();
            s[tid] += t;
            __syncthreads();
        }
        int c = carry;
        if (i < n) {
            int incl = s[tid];
            row_ptr[i + 1] = c + incl;
            cursor[i] = c + incl - v;
        }
        __syncthreads();
        if (tid == 0) carry = c + s[1023];
        __syncthreads();
    }
}

__global__ void fill_csr_kernel(const void* __restrict__ ei, int E,
                                int* __restrict__ cursor, int* __restrict__ csr_src) {
    int e = blockIdx.x * blockDim.x + threadIdx.x;
    if (e < E) {
        int is64 = g_is64;
        int d = get_idx(ei, E + e, is64);
        int s = get_idx(ei, e, is64);
        int pos = atomicAdd(&cursor[d], 1);
        csr_src[pos] = s;
    }
}

__global__ void scan_graphs_kernel(const int* __restrict__ gcnt, int* __restrict__ gstart) {
    __shared__ int s[NGRAPH];
    int tid = threadIdx.x;
    s[tid] = gcnt[tid];
    __syncthreads();
    for (int off = 1; off < NGRAPH; off <<= 1) {
        int t = (tid >= off) ? s[tid - off] : 0;
        __syncthreads();
        s[tid] += t;
        __syncthreads();
    }
    if (tid == 0) gstart[0] = 0;
    gstart[tid + 1] = s[tid];
}

// ---------------- tiled SGEMM: C[M,256] = A[M,K] @ B[K,256] (+bias[col]) (*scale[row]) ----------------
#define BM 128
#define BN 128
#define BK 8
#define TM 8
#define TN 8

__global__ __launch_bounds__(256) void sgemm_kernel(
    const float* __restrict__ A, const float* __restrict__ B, float* __restrict__ C,
    int M, int K, const float* __restrict__ bias, const float* __restrict__ scale) {
    __shared__ float As[BK][BM];
    __shared__ float Bs[BK][BN];
    const int N = HID;
    const int tid = threadIdx.x;
    const int colBase = blockIdx.x * BN;
    const int rowBase = blockIdx.y * BM;
    const int threadCol = tid % (BN / TN);  // 0..15
    const int threadRow = tid / (BN / TN);  // 0..15

    const int innerRowA = tid >> 1;          // 0..127
    const int innerColA = (tid & 1) * 4;     // 0 or 4
    const int innerRowB = tid >> 5;          // 0..7
    const int innerColB = (tid & 31) * 4;    // 0..124

    float acc[TM][TN];
#pragma unroll
    for (int i = 0; i < TM; i++)
#pragma unroll
        for (int j = 0; j < TN; j++) acc[i][j] = 0.0f;

    float regM[TM], regN[TN];

    for (int k0 = 0; k0 < K; k0 += BK) {
        int ar = rowBase + innerRowA;
        float4 a4 = make_float4(0.f, 0.f, 0.f, 0.f);
        if (ar < M)
            a4 = *reinterpret_cast<const float4*>(&A[(size_t)ar * K + k0 + innerColA]);
        As[innerColA + 0][innerRowA] = a4.x;
        As[innerColA + 1][innerRowA] = a4.y;
        As[innerColA + 2][innerRowA] = a4.z;
        As[innerColA + 3][innerRowA] = a4.w;

        float4 b4 = *reinterpret_cast<const float4*>(&B[(size_t)(k0 + innerRowB) * N + colBase + innerColB]);
        *reinterpret_cast<float4*>(&Bs[innerRowB][innerColB]) = b4;
        __syncthreads();

#pragma unroll
        for (int k = 0; k < BK; k++) {
#pragma unroll
            for (int i = 0; i < TM; i++) regM[i] = As[k][threadRow * TM + i];
#pragma unroll
            for (int j = 0; j < TN; j++) regN[j] = Bs[k][threadCol * TN + j];
#pragma unroll
            for (int i = 0; i < TM; i++)
#pragma unroll
                for (int j = 0; j < TN; j++) acc[i][j] += regM[i] * regN[j];
        }
        __syncthreads();
    }

#pragma unroll
    for (int i = 0; i < TM; i++) {
        int r = rowBase + threadRow * TM + i;
        if (r < M) {
            float s = scale ? scale[r] : 1.0f;
#pragma unroll
            for (int j = 0; j < TN; j += 4) {
                int c = colBase + threadCol * TN + j;
                float4 v;
                v.x = acc[i][j + 0];
                v.y = acc[i][j + 1];
                v.z = acc[i][j + 2];
                v.w = acc[i][j + 3];
                if (bias) {
                    v.x += bias[c + 0];
                    v.y += bias[c + 1];
                    v.z += bias[c + 2];
                    v.w += bias[c + 3];
                }
                v.x *= s; v.y *= s; v.z *= s; v.w *= s;
                *reinterpret_cast<float4*>(&C[(size_t)r * N + c]) = v;
            }
        }
    }
}

// ---------------- gather: out[d,:] = relu(dinv[d]*(sum_{src in CSR[d]} hp[src,:] + hp[d,:]) + b[:]) ----------------
__global__ void gather_kernel(const float* __restrict__ hp, float* __restrict__ out,
                              const int* __restrict__ row_ptr, const int* __restrict__ csr_src,
                              const float* __restrict__ dinv, const float* __restrict__ bias, int n) {
    int warp = (blockIdx.x * blockDim.x + threadIdx.x) >> 5;
    int lane = threadIdx.x & 31;
    if (warp >= n) return;
    int beg = row_ptr[warp];
    int end = row_ptr[warp + 1];
    float acc[8];
#pragma unroll
    for (int j = 0; j < 8; j++) acc[j] = 0.0f;

    for (int e = beg; e < end; e++) {
        int src = csr_src[e];
        const float* row = hp + (size_t)src * HID;
#pragma unroll
        for (int j = 0; j < 8; j++) acc[j] += __ldg(&row[lane + 32 * j]);
    }
    const float* selfrow = hp + (size_t)warp * HID;
    float dv = dinv[warp];
#pragma unroll
    for (int j = 0; j < 8; j++) {
        int c = lane + 32 * j;
        float v = dv * (acc[j] + selfrow[c]) + bias[c];
        out[(size_t)warp * HID + c] = fmaxf(v, 0.0f);
    }
}

// ---------------- pooling (batch is sorted -> contiguous ranges) ----------------
__global__ void pool_mean_kernel(const float* __restrict__ h, const int* __restrict__ gstart,
                                 float* __restrict__ pooled) {
    int g = blockIdx.x;       // 128 blocks
    int t = threadIdx.x;      // 256 threads, one per column
    int beg = gstart[g];
    int end = gstart[g + 1];
    float sum = 0.0f;
    for (int i = beg; i < end; i++) sum += h[(size_t)i * HID + t];
    float c = (float)(end - beg);
    pooled[g * HID + t] = sum / fmaxf(c, 1.0f);
}

__global__ void out_gemm_kernel(const float* __restrict__ pooled, const float* __restrict__ W,
                                const float* __restrict__ b, float* __restrict__ out) {
    int idx = blockIdx.x * blockDim.x + threadIdx.x;
    if (idx >= NGRAPH * NCLS) return;
    int g = idx >> 4;
    int c = idx & 15;
    float s = b[c];
#pragma unroll 8
    for (int k = 0; k < HID; k++) s += pooled[g * HID + k] * W[k * NCLS + c];
    out[idx] = s;
}

// ---------------- launch ----------------
extern "C" void kernel_launch(void* const* d_in, const int* in_sizes, int n_in,
                              void* d_out, int out_size) {
    const float* x     = (const float*)d_in[0];
    const void*  ei    = d_in[1];
    const void*  batch = d_in[2];
    const float* W_in  = (const float*)d_in[3];
    const float* b_in  = (const float*)d_in[4];
    const float* W1    = (const float*)d_in[5];
    const float* b1    = (const float*)d_in[6];
    const float* W2    = (const float*)d_in[7];
    const float* b2    = (const float*)d_in[8];
    const float* W_out = (const float*)d_in[9];
    const float* b_out = (const float*)d_in[10];

    const int N = in_sizes[0] / INDIM;   // 50000
    const int E = in_sizes[1] / 2;       // 800000

    float *bufA, *bufB, *dinv, *pool;
    int *indeg, *row_ptr, *cursor, *csr_src, *gcnt, *gstart;
    cudaGetSymbolAddress((void**)&bufA, g_bufA);
    cudaGetSymbolAddress((void**)&bufB, g_bufB);
    cudaGetSymbolAddress((void**)&dinv, g_dinv);
    cudaGetSymbolAddress((void**)&pool, g_pool);
    cudaGetSymbolAddress((void**)&indeg, g_indeg);
    cudaGetSymbolAddress((void**)&row_ptr, g_row_ptr);
    cudaGetSymbolAddress((void**)&cursor, g_cursor);
    cudaGetSymbolAddress((void**)&csr_src, g_csr_src);
    cudaGetSymbolAddress((void**)&gcnt, g_gcnt);
    cudaGetSymbolAddress((void**)&gstart, g_gstart);

    // dtype detection: sample 4096 odd 32-bit words of edge_index
    detect_dtype_kernel<<<1, 256>>>((const int*)ei, 4096);

    // degree histogram + graph histogram
    zero_int_kernel<<<(N + 255) / 256, 256>>>(indeg, N);
    zero_int_kernel<<<1, NGRAPH>>>(gcnt, NGRAPH);
    hist_dst_kernel<<<(E + 255) / 256, 256>>>(ei, E, indeg);
    hist_batch_kernel<<<(N + 255) / 256, 256>>>(batch, N, gcnt);

    // CSR build + dinv
    scan_kernel<<<1, 1024>>>(indeg, row_ptr, cursor, N);
    dinv_kernel<<<(N + 255) / 256, 256>>>(indeg, dinv, N);
    fill_csr_kernel<<<(E + 255) / 256, 256>>>(ei, E, cursor, csr_src);
    scan_graphs_kernel<<<1, NGRAPH>>>(gcnt, gstart);

    dim3 ggrid(HID / BN, (N + BM - 1) / BM);

    // input layer: bufA = x @ W_in + b_in
    sgemm_kernel<<<ggrid, 256>>>(x, W_in, bufA, N, INDIM, b_in, nullptr);

    // layer 1: bufB = dinv * (bufA @ W1); bufA = relu(dinv[d]*(sum + self) + b1)
    sgemm_kernel<<<ggrid, 256>>>(bufA, W1, bufB, N, HID, nullptr, dinv);
    gather_kernel<<<(N * 32 + 255) / 256, 256>>>(bufB, bufA, row_ptr, csr_src, dinv, b1, N);

    // layer 2
    sgemm_kernel<<<ggrid, 256>>>(bufA, W2, bufB, N, HID, nullptr, dinv);
    gather_kernel<<<(N * 32 + 255) / 256, 256>>>(bufB, bufA, row_ptr, csr_src, dinv, b2, N);

    // pooling + output head
    pool_mean_kernel<<<NGRAPH, HID>>>(bufA, gstart, pool);
    out_gemm_kernel<<<(NGRAPH * NCLS + 255) / 256, 256>>>(pool, W_out, b_out, (float*)d_out);
}

// round 3
// speedup vs baseline: 1.1706x; 1.1706x over previous
#include <cuda_runtime.h>
#include <cuda_bf16.h>

// Problem constants
#define NNODES 50000
#define NEDGES 800000
#define INDIM  128
#define HID    256
#define NGRAPH 128
#define NCLS   16

// ---------------- device scratch (no cudaMalloc allowed) ----------------
__device__ float g_bufA[NNODES * HID];
__device__ float g_bufB[NNODES * HID];
__device__ float g_dinv[NNODES];
__device__ int   g_indeg[NNODES];
__device__ int   g_row_ptr[NNODES + 1];
__device__ int   g_cursor[NNODES];
__device__ int   g_csr_src[NEDGES];
__device__ int   g_gcnt[NGRAPH];
__device__ int   g_gstart[NGRAPH + 1];
__device__ float g_pool[NGRAPH * HID];
__device__ int   g_is64;   // 1 if indices are int64, 0 if int32

__device__ __forceinline__ int get_idx(const void* p, int i, int is64) {
    if (is64) return (int)((const long long*)p)[i];
    return ((const int*)p)[i];
}

// ---------------- dtype detection ----------------
__global__ void detect_dtype_kernel(const int* __restrict__ w, int nOddSamples) {
    __shared__ int found;
    if (threadIdx.x == 0) found = 0;
    __syncthreads();
    for (int i = threadIdx.x; i < nOddSamples; i += blockDim.x) {
        if (w[2 * i + 1] != 0) found = 1;
    }
    __syncthreads();
    if (threadIdx.x == 0) g_is64 = found ? 0 : 1;
}

// ---------------- small utility kernels ----------------
__global__ void zero_int_kernel(int* p, int n) {
    int i = blockIdx.x * blockDim.x + threadIdx.x;
    if (i < n) p[i] = 0;
}

__global__ void hist_dst_kernel(const void* __restrict__ ei, int E, int* __restrict__ indeg) {
    int e = blockIdx.x * blockDim.x + threadIdx.x;
    if (e < E) {
        int d = get_idx(ei, E + e, g_is64);
        atomicAdd(&indeg[d], 1);
    }
}

__global__ void hist_batch_kernel(const void* __restrict__ batch, int n, int* __restrict__ gcnt) {
    int i = blockIdx.x * blockDim.x + threadIdx.x;
    if (i < n) {
        int g = get_idx(batch, i, g_is64);
        atomicAdd(&gcnt[g], 1);
    }
}

__global__ void dinv_kernel(const int* __restrict__ indeg, float* __restrict__ dinv, int n) {
    int i = blockIdx.x * blockDim.x + threadIdx.x;
    if (i < n) dinv[i] = rsqrtf((float)indeg[i] + 1.0f);
}

__global__ void scan_kernel(const int* __restrict__ counts, int* __restrict__ row_ptr,
                            int* __restrict__ cursor, int n) {
    __shared__ int s[1024];
    __shared__ int carry;
    int tid = threadIdx.x;
    if (tid == 0) { carry = 0; row_ptr[0] = 0; }
    __syncthreads();
    for (int base = 0; base < n; base += 1024) {
        int i = base + tid;
        int v = (i < n) ? counts[i] : 0;
        s[tid] = v;
        __syncthreads();
        for (int off = 1; off < 1024; off <<= 1) {
            int t = (tid >= off) ? s[tid - off] : 0;
            __syncthreads();
            s[tid] += t;
            __syncthreads();
        }
        int c = carry;
        if (i < n) {
            int incl = s[tid];
            row_ptr[i + 1] = c + incl;
            cursor[i] = c + incl - v;
        }
        __syncthreads();
        if (tid == 0) carry = c + s[1023];
        __syncthreads();
    }
}

__global__ void fill_csr_kernel(const void* __restrict__ ei, int E,
                                int* __restrict__ cursor, int* __restrict__ csr_src) {
    int e = blockIdx.x * blockDim.x + threadIdx.x;
    if (e < E) {
        int is64 = g_is64;
        int d = get_idx(ei, E + e, is64);
        int s = get_idx(ei, e, is64);
        int pos = atomicAdd(&cursor[d], 1);
        csr_src[pos] = s;
    }
}

__global__ void scan_graphs_kernel(const int* __restrict__ gcnt, int* __restrict__ gstart) {
    __shared__ int s[NGRAPH];
    int tid = threadIdx.x;
    s[tid] = gcnt[tid];
    __syncthreads();
    for (int off = 1; off < NGRAPH; off <<= 1) {
        int t = (tid >= off) ? s[tid - off] : 0;
        __syncthreads();
        s[tid] += t;
        __syncthreads();
    }
    if (tid == 0) gstart[0] = 0;
    gstart[tid + 1] = s[tid];
}

// ---------------- SGEMM: C[M,256] = A[M,K] @ B[K,256] (+bias[col]) (*scale[row]) ----------------
// BM=128, BN=128, BK=16, 256 threads, 8x8 per thread in split 4+4 fragments,
// register-prefetch double buffering.
#define BM 128
#define BN 128
#define BK 16
#define AS_STRIDE 132   // padded row stride for transposed A tile (16B aligned, reduces STS conflicts)

__global__ __launch_bounds__(256, 2) void sgemm_kernel(
    const float* __restrict__ A, const float* __restrict__ B, float* __restrict__ C,
    int M, int K, const float* __restrict__ bias, const float* __restrict__ scale) {
    __shared__ float As[BK * AS_STRIDE];   // As[k][m]
    __shared__ float Bs[BK * BN];          // Bs[k][n]

    const int tid = threadIdx.x;
    const int colBase = blockIdx.x * BN;
    const int rowBase = blockIdx.y * BM;

    const int tr = tid >> 4;    // 0..15
    const int tc = tid & 15;    // 0..15
    const int rm0 = tr * 4, rm1 = 64 + tr * 4;
    const int cn0 = tc * 4, cn1 = 64 + tc * 4;

    // A tile loads: 128 rows x 16 cols = 512 float4, 2 per thread
    const int aRow0 = tid >> 2;            // 0..63
    const int aRow1 = 64 + (tid >> 2);     // 64..127
    const int aC = (tid & 3) * 4;          // 0,4,8,12
    // B tile loads: 16 rows x 128 cols = 512 float4, 2 per thread
    const int bRow0 = tid >> 5;            // 0..7
    const int bRow1 = 8 + (tid >> 5);      // 8..15
    const int bCol = (tid & 31) * 4;       // 0..124

    // clamp A rows (OOB rows produce garbage acc that is never stored)
    int gr0 = rowBase + aRow0; gr0 = gr0 < M ? gr0 : M - 1;
    int gr1 = rowBase + aRow1; gr1 = gr1 < M ? gr1 : M - 1;
    const float* aPtr0 = A + (size_t)gr0 * K + aC;
    const float* aPtr1 = A + (size_t)gr1 * K + aC;
    const float* bPtr0 = B + (size_t)bRow0 * HID + colBase + bCol;
    const float* bPtr1 = B + (size_t)bRow1 * HID + colBase + bCol;

    float acc[8][8];
#pragma unroll
    for (int i = 0; i < 8; i++)
#pragma unroll
        for (int j = 0; j < 8; j++) acc[i][j] = 0.0f;

    const int nt = K / BK;

    // prologue: load tile 0
    float4 pa0 = *reinterpret_cast<const float4*>(aPtr0);
    float4 pa1 = *reinterpret_cast<const float4*>(aPtr1);
    float4 pb0 = *reinterpret_cast<const float4*>(bPtr0);
    float4 pb1 = *reinterpret_cast<const float4*>(bPtr1);

    for (int t = 0; t < nt; t++) {
        // store current tile to smem
        As[(aC + 0) * AS_STRIDE + aRow0] = pa0.x;
        As[(aC + 1) * AS_STRIDE + aRow0] = pa0.y;
        As[(aC + 2) * AS_STRIDE + aRow0] = pa0.z;
        As[(aC + 3) * AS_STRIDE + aRow0] = pa0.w;
        As[(aC + 0) * AS_STRIDE + aRow1] = pa1.x;
        As[(aC + 1) * AS_STRIDE + aRow1] = pa1.y;
        As[(aC + 2) * AS_STRIDE + aRow1] = pa1.z;
        As[(aC + 3) * AS_STRIDE + aRow1] = pa1.w;
        *reinterpret_cast<float4*>(&Bs[bRow0 * BN + bCol]) = pb0;
        *reinterpret_cast<float4*>(&Bs[bRow1 * BN + bCol]) = pb1;
        __syncthreads();

        // prefetch next tile into registers
        if (t + 1 < nt) {
            int k0 = (t + 1) * BK;
            pa0 = *reinterpret_cast<const float4*>(aPtr0 + k0);
            pa1 = *reinterpret_cast<const float4*>(aPtr1 + k0);
            pb0 = *reinterpret_cast<const float4*>(bPtr0 + (size_t)k0 * HID);
            pb1 = *reinterpret_cast<const float4*>(bPtr1 + (size_t)k0 * HID);
        }

        // compute 16 k-steps
#pragma unroll
        for (int k = 0; k < BK; k++) {
            float4 m0 = *reinterpret_cast<const float4*>(&As[k * AS_STRIDE + rm0]);
            float4 m1 = *reinterpret_cast<const float4*>(&As[k * AS_STRIDE + rm1]);
            float4 n0 = *reinterpret_cast<const float4*>(&Bs[k * BN + cn0]);
            float4 n1 = *reinterpret_cast<const float4*>(&Bs[k * BN + cn1]);
            float rm[8] = {m0.x, m0.y, m0.z, m0.w, m1.x, m1.y, m1.z, m1.w};
            float rn[8] = {n0.x, n0.y, n0.z, n0.w, n1.x, n1.y, n1.z, n1.w};
#pragma unroll
            for (int i = 0; i < 8; i++)
#pragma unroll
                for (int j = 0; j < 8; j++) acc[i][j] += rm[i] * rn[j];
        }
        __syncthreads();
    }

    // epilogue
#pragma unroll
    for (int i = 0; i < 8; i++) {
        int r = rowBase + ((i < 4) ? (rm0 + i) : (rm1 + i - 4));
        if (r < M) {
            float s = scale ? scale[r] : 1.0f;
            float4 v0, v1;
            v0.x = acc[i][0]; v0.y = acc[i][1]; v0.z = acc[i][2]; v0.w = acc[i][3];
            v1.x = acc[i][4]; v1.y = acc[i][5]; v1.z = acc[i][6]; v1.w = acc[i][7];
            int c0 = colBase + cn0;
            int c1 = colBase + cn1;
            if (bias) {
                v0.x += bias[c0 + 0]; v0.y += bias[c0 + 1]; v0.z += bias[c0 + 2]; v0.w += bias[c0 + 3];
                v1.x += bias[c1 + 0]; v1.y += bias[c1 + 1]; v1.z += bias[c1 + 2]; v1.w += bias[c1 + 3];
            }
            v0.x *= s; v0.y *= s; v0.z *= s; v0.w *= s;
            v1.x *= s; v1.y *= s; v1.z *= s; v1.w *= s;
            *reinterpret_cast<float4*>(&C[(size_t)r * HID + c0]) = v0;
            *reinterpret_cast<float4*>(&C[(size_t)r * HID + c1]) = v1;
        }
    }
}

// ---------------- gather: out[d,:] = relu(dinv[d]*(sum_{src in CSR[d]} hp[src,:] + hp[d,:]) + b[:]) ----------------
__global__ void gather_kernel(const float* __restrict__ hp, float* __restrict__ out,
                              const int* __restrict__ row_ptr, const int* __restrict__ csr_src,
                              const float* __restrict__ dinv, const float* __restrict__ bias, int n) {
    int warp = (blockIdx.x * blockDim.x + threadIdx.x) >> 5;
    int lane = threadIdx.x & 31;
    if (warp >= n) return;
    int beg = row_ptr[warp];
    int end = row_ptr[warp + 1];
    float acc[8];
#pragma unroll
    for (int j = 0; j < 8; j++) acc[j] = 0.0f;

    for (int e = beg; e < end; e++) {
        int src = csr_src[e];
        const float* row = hp + (size_t)src * HID;
#pragma unroll
        for (int j = 0; j < 8; j++) acc[j] += __ldg(&row[lane + 32 * j]);
    }
    const float* selfrow = hp + (size_t)warp * HID;
    float dv = dinv[warp];
#pragma unroll
    for (int j = 0; j < 8; j++) {
        int c = lane + 32 * j;
        float v = dv * (acc[j] + selfrow[c]) + bias[c];
        out[(size_t)warp * HID + c] = fmaxf(v, 0.0f);
    }
}

// ---------------- pooling (batch is sorted -> contiguous ranges) ----------------
__global__ void pool_mean_kernel(const float* __restrict__ h, const int* __restrict__ gstart,
                                 float* __restrict__ pooled) {
    int g = blockIdx.x;
    int t = threadIdx.x;
    int beg = gstart[g];
    int end = gstart[g + 1];
    float sum = 0.0f;
    for (int i = beg; i < end; i++) sum += h[(size_t)i * HID + t];
    float c = (float)(end - beg);
    pooled[g * HID + t] = sum / fmaxf(c, 1.0f);
}

__global__ void out_gemm_kernel(const float* __restrict__ pooled, const float* __restrict__ W,
                                const float* __restrict__ b, float* __restrict__ out) {
    int idx = blockIdx.x * blockDim.x + threadIdx.x;
    if (idx >= NGRAPH * NCLS) return;
    int g = idx >> 4;
    int c = idx & 15;
    float s = b[c];
#pragma unroll 8
    for (int k = 0; k < HID; k++) s += pooled[g * HID + k] * W[k * NCLS + c];
    out[idx] = s;
}

// ---------------- launch ----------------
extern "C" void kernel_launch(void* const* d_in, const int* in_sizes, int n_in,
                              void* d_out, int out_size) {
    const float* x     = (const float*)d_in[0];
    const void*  ei    = d_in[1];
    const void*  batch = d_in[2];
    const float* W_in  = (const float*)d_in[3];
    const float* b_in  = (const float*)d_in[4];
    const float* W1    = (const float*)d_in[5];
    const float* b1    = (const float*)d_in[6];
    const float* W2    = (const float*)d_in[7];
    const float* b2    = (const float*)d_in[8];
    const float* W_out = (const float*)d_in[9];
    const float* b_out = (const float*)d_in[10];

    const int N = in_sizes[0] / INDIM;   // 50000
    const int E = in_sizes[1] / 2;       // 800000

    float *bufA, *bufB, *dinv, *pool;
    int *indeg, *row_ptr, *cursor, *csr_src, *gcnt, *gstart;
    cudaGetSymbolAddress((void**)&bufA, g_bufA);
    cudaGetSymbolAddress((void**)&bufB, g_bufB);
    cudaGetSymbolAddress((void**)&dinv, g_dinv);
    cudaGetSymbolAddress((void**)&pool, g_pool);
    cudaGetSymbolAddress((void**)&indeg, g_indeg);
    cudaGetSymbolAddress((void**)&row_ptr, g_row_ptr);
    cudaGetSymbolAddress((void**)&cursor, g_cursor);
    cudaGetSymbolAddress((void**)&csr_src, g_csr_src);
    cudaGetSymbolAddress((void**)&gcnt, g_gcnt);
    cudaGetSymbolAddress((void**)&gstart, g_gstart);

    detect_dtype_kernel<<<1, 256>>>((const int*)ei, 4096);

    zero_int_kernel<<<(N + 255) / 256, 256>>>(indeg, N);
    zero_int_kernel<<<1, NGRAPH>>>(gcnt, NGRAPH);
    hist_dst_kernel<<<(E + 255) / 256, 256>>>(ei, E, indeg);
    hist_batch_kernel<<<(N + 255) / 256, 256>>>(batch, N, gcnt);

    scan_kernel<<<1, 1024>>>(indeg, row_ptr, cursor, N);
    dinv_kernel<<<(N + 255) / 256, 256>>>(indeg, dinv, N);
    fill_csr_kernel<<<(E + 255) / 256, 256>>>(ei, E, cursor, csr_src);
    scan_graphs_kernel<<<1, NGRAPH>>>(gcnt, gstart);

    dim3 ggrid(HID / BN, (N + BM - 1) / BM);

    sgemm_kernel<<<ggrid, 256>>>(x, W_in, bufA, N, INDIM, b_in, nullptr);

    sgemm_kernel<<<ggrid, 256>>>(bufA, W1, bufB, N, HID, nullptr, dinv);
    gather_kernel<<<(N * 32 + 255) / 256, 256>>>(bufB, bufA, row_ptr, csr_src, dinv, b1, N);

    sgemm_kernel<<<ggrid, 256>>>(bufA, W2, bufB, N, HID, nullptr, dinv);
    gather_kernel<<<(N * 32 + 255) / 256, 256>>>(bufB, bufA, row_ptr, csr_src, dinv, b2, N);

    pool_mean_kernel<<<NGRAPH, HID>>>(bufA, gstart, pool);
    out_gemm_kernel<<<(NGRAPH * NCLS + 255) / 256, 256>>>(pool, W_out, b_out, (float*)d_out);
}

// round 4
// speedup vs baseline: 1.8630x; 1.5915x over previous
#include <cuda_runtime.h>
#include <cuda_bf16.h>
#include <cstdint>

// Problem constants
#define NNODES 50000
#define NEDGES 800000
#define INDIM  128
#define HID    256
#define NGRAPH 128
#define NCLS   16

// ---------------- device scratch (no cudaMalloc allowed) ----------------
__device__ float g_bufA[NNODES * HID];
__device__ float g_bufB[NNODES * HID];
__device__ float g_dinv[NNODES];
__device__ int   g_indeg[NNODES];
__device__ int   g_row_ptr[NNODES + 1];
__device__ int   g_cursor[NNODES];
__device__ int   g_csr_src[NEDGES];
__device__ int   g_localscan[NNODES];
__device__ int   g_blocksum[64];
__device__ int   g_blockoff[64];
__device__ int   g_gcnt[NGRAPH];
__device__ int   g_gstart[NGRAPH + 1];
__device__ float g_pool[NGRAPH * HID];
__device__ int   g_is64;

__device__ __forceinline__ int get_idx(const void* p, int i, int is64) {
    if (is64) return (int)((const long long*)p)[i];
    return ((const int*)p)[i];
}

__device__ __forceinline__ uint32_t f2tf32(float f) {
    uint32_t u;
    asm("cvt.rna.tf32.f32 %0, %1;" : "=r"(u) : "f"(f));
    return u;
}

// ---------------- dtype detection ----------------
__global__ void detect_dtype_kernel(const int* __restrict__ w, int nOddSamples) {
    __shared__ int found;
    if (threadIdx.x == 0) found = 0;
    __syncthreads();
    for (int i = threadIdx.x; i < nOddSamples; i += blockDim.x) {
        if (w[2 * i + 1] != 0) found = 1;
    }
    __syncthreads();
    if (threadIdx.x == 0) g_is64 = found ? 0 : 1;
}

// ---------------- small utility kernels ----------------
__global__ void zero_int_kernel(int* p, int n) {
    int i = blockIdx.x * blockDim.x + threadIdx.x;
    if (i < n) p[i] = 0;
}

__global__ void hist_dst_kernel(const void* __restrict__ ei, int E, int* __restrict__ indeg) {
    int e = blockIdx.x * blockDim.x + threadIdx.x;
    if (e < E) {
        int d = get_idx(ei, E + e, g_is64);
        atomicAdd(&indeg[d], 1);
    }
}

__global__ void hist_batch_kernel(const void* __restrict__ batch, int n, int* __restrict__ gcnt) {
    int i = blockIdx.x * blockDim.x + threadIdx.x;
    if (i < n) {
        int g = get_idx(batch, i, g_is64);
        atomicAdd(&gcnt[g], 1);
    }
}

__global__ void dinv_kernel(const int* __restrict__ indeg, float* __restrict__ dinv, int n) {
    int i = blockIdx.x * blockDim.x + threadIdx.x;
    if (i < n) dinv[i] = rsqrtf((float)indeg[i] + 1.0f);
}

// ---------------- multi-block scan ----------------
__global__ void scan_local_kernel(const int* __restrict__ counts, int* __restrict__ localscan, int n) {
    __shared__ int s[1024];
    int tid = threadIdx.x;
    int i = blockIdx.x * 1024 + tid;
    int v = (i < n) ? counts[i] : 0;
    s[tid] = v;
    __syncthreads();
    for (int off = 1; off < 1024; off <<= 1) {
        int t = (tid >= off) ? s[tid - off] : 0;
        __syncthreads();
        s[tid] += t;
        __syncthreads();
    }
    if (i < n) localscan[i] = s[tid];
    if (tid == 1023) g_blocksum[blockIdx.x] = s[1023];
}

__global__ void scan_blocksums_kernel(int nb) {
    __shared__ int s[64];
    int tid = threadIdx.x;
    int v = (tid < nb) ? g_blocksum[tid] : 0;
    s[tid] = v;
    __syncthreads();
    for (int off = 1; off < 64; off <<= 1) {
        int t = (tid >= off) ? s[tid - off] : 0;
        __syncthreads();
        s[tid] += t;
        __syncthreads();
    }
    g_blockoff[tid] = s[tid] - v;   // exclusive offset
}

__global__ void scan_finalize_kernel(const int* __restrict__ counts, const int* __restrict__ localscan,
                                     int* __restrict__ row_ptr, int* __restrict__ cursor, int n) {
    int i = blockIdx.x * blockDim.x + threadIdx.x;
    if (i < n) {
        int incl = localscan[i] + g_blockoff[i >> 10];
        row_ptr[i + 1] = incl;
        cursor[i] = incl - counts[i];
        if (i == 0) row_ptr[0] = 0;
    }
}

__global__ void fill_csr_kernel(const void* __restrict__ ei, int E,
                                int* __restrict__ cursor, int* __restrict__ csr_src) {
    int e = blockIdx.x * blockDim.x + threadIdx.x;
    if (e < E) {
        int is64 = g_is64;
        int d = get_idx(ei, E + e, is64);
        int s = get_idx(ei, e, is64);
        int pos = atomicAdd(&cursor[d], 1);
        csr_src[pos] = s;
    }
}

__global__ void scan_graphs_kernel(const int* __restrict__ gcnt, int* __restrict__ gstart) {
    __shared__ int s[NGRAPH];
    int tid = threadIdx.x;
    s[tid] = gcnt[tid];
    __syncthreads();
    for (int off = 1; off < NGRAPH; off <<= 1) {
        int t = (tid >= off) ? s[tid - off] : 0;
        __syncthreads();
        s[tid] += t;
        __syncthreads();
    }
    if (tid == 0) gstart[0] = 0;
    gstart[tid + 1] = s[tid];
}

// ---------------- TF32 tensor-core GEMM ----------------
// C[M,256] = A[M,K] @ B[K,256]  (+bias[col]) (*scale[row])
// Block tile 128x128, BK=16. 256 threads = 8 warps (4x2). Warp tile 32x64.
// mma.sync.aligned.m16n8k8.row.col.f32.tf32.tf32.f32
#define BM 128
#define BN 128
#define BK 16
#define AS_K 20     // A smem: [m][k], row stride 20 words (conflict-free frag loads)
#define BS_N 136    // B smem: [k][n], row stride 136 words (conflict-free frag loads)

__global__ __launch_bounds__(256, 2) void tf32gemm_kernel(
    const float* __restrict__ A, const float* __restrict__ B, float* __restrict__ C,
    int M, int K, const float* __restrict__ bias, const float* __restrict__ scale) {
    __shared__ uint32_t As[BM * AS_K];   // As[m][k]
    __shared__ uint32_t Bs[BK * BS_N];   // Bs[k][n]

    const int tid = threadIdx.x;
    const int colBase = blockIdx.x * BN;
    const int rowBase = blockIdx.y * BM;

    const int wid = tid >> 5;
    const int lane = tid & 31;
    const int warpM = wid & 3;          // 0..3
    const int warpN = wid >> 2;         // 0..1
    const int g = lane >> 2;            // 0..7
    const int t4 = lane & 3;            // 0..3
    const int mB = warpM * 32;
    const int nB = warpN * 64;

    // gmem load indexing
    const int aRow0 = tid >> 2;            // 0..63
    const int aRow1 = 64 + (tid >> 2);     // 64..127
    const int aC = (tid & 3) * 4;          // 0,4,8,12
    const int bRow0 = tid >> 5;            // 0..7
    const int bRow1 = 8 + (tid >> 5);      // 8..15
    const int bCol = (tid & 31) * 4;       // 0..124

    int gr0 = rowBase + aRow0; gr0 = gr0 < M ? gr0 : M - 1;
    int gr1 = rowBase + aRow1; gr1 = gr1 < M ? gr1 : M - 1;
    const float* aPtr0 = A + (size_t)gr0 * K + aC;
    const float* aPtr1 = A + (size_t)gr1 * K + aC;
    const float* bPtr0 = B + (size_t)bRow0 * HID + colBase + bCol;
    const float* bPtr1 = B + (size_t)bRow1 * HID + colBase + bCol;

    float acc[2][8][4];
#pragma unroll
    for (int mt = 0; mt < 2; mt++)
#pragma unroll
        for (int nt = 0; nt < 8; nt++)
#pragma unroll
            for (int c = 0; c < 4; c++) acc[mt][nt][c] = 0.0f;

    const int nTiles = K / BK;

    float4 pa0 = *reinterpret_cast<const float4*>(aPtr0);
    float4 pa1 = *reinterpret_cast<const float4*>(aPtr1);
    float4 pb0 = *reinterpret_cast<const float4*>(bPtr0);
    float4 pb1 = *reinterpret_cast<const float4*>(bPtr1);

    for (int t = 0; t < nTiles; t++) {
        // convert + store to smem
        {
            uint4 ua0 = make_uint4(f2tf32(pa0.x), f2tf32(pa0.y), f2tf32(pa0.z), f2tf32(pa0.w));
            uint4 ua1 = make_uint4(f2tf32(pa1.x), f2tf32(pa1.y), f2tf32(pa1.z), f2tf32(pa1.w));
            uint4 ub0 = make_uint4(f2tf32(pb0.x), f2tf32(pb0.y), f2tf32(pb0.z), f2tf32(pb0.w));
            uint4 ub1 = make_uint4(f2tf32(pb1.x), f2tf32(pb1.y), f2tf32(pb1.z), f2tf32(pb1.w));
            *reinterpret_cast<uint4*>(&As[aRow0 * AS_K + aC]) = ua0;
            *reinterpret_cast<uint4*>(&As[aRow1 * AS_K + aC]) = ua1;
            *reinterpret_cast<uint4*>(&Bs[bRow0 * BS_N + bCol]) = ub0;
            *reinterpret_cast<uint4*>(&Bs[bRow1 * BS_N + bCol]) = ub1;
        }
        __syncthreads();

        // prefetch next tile
        if (t + 1 < nTiles) {
            int k0 = (t + 1) * BK;
            pa0 = *reinterpret_cast<const float4*>(aPtr0 + k0);
            pa1 = *reinterpret_cast<const float4*>(aPtr1 + k0);
            pb0 = *reinterpret_cast<const float4*>(bPtr0 + (size_t)k0 * HID);
            pb1 = *reinterpret_cast<const float4*>(bPtr1 + (size_t)k0 * HID);
        }

        // two k8 mma steps
#pragma unroll
        for (int ks = 0; ks < BK; ks += 8) {
            uint32_t af[2][4];
#pragma unroll
            for (int mt = 0; mt < 2; mt++) {
                int m0 = mB + mt * 16 + g;
                af[mt][0] = As[m0 * AS_K + ks + t4];
                af[mt][1] = As[(m0 + 8) * AS_K + ks + t4];
                af[mt][2] = As[m0 * AS_K + ks + t4 + 4];
                af[mt][3] = As[(m0 + 8) * AS_K + ks + t4 + 4];
            }
            uint32_t bf[8][2];
#pragma unroll
            for (int nt = 0; nt < 8; nt++) {
                int n0 = nB + nt * 8 + g;
                bf[nt][0] = Bs[(ks + t4) * BS_N + n0];
                bf[nt][1] = Bs[(ks + t4 + 4) * BS_N + n0];
            }
#pragma unroll
            for (int mt = 0; mt < 2; mt++)
#pragma unroll
                for (int nt = 0; nt < 8; nt++) {
                    asm volatile(
                        "mma.sync.aligned.m16n8k8.row.col.f32.tf32.tf32.f32 "
                        "{%0,%1,%2,%3}, {%4,%5,%6,%7}, {%8,%9}, {%0,%1,%2,%3};"
                        : "+f"(acc[mt][nt][0]), "+f"(acc[mt][nt][1]),
                          "+f"(acc[mt][nt][2]), "+f"(acc[mt][nt][3])
                        : "r"(af[mt][0]), "r"(af[mt][1]), "r"(af[mt][2]), "r"(af[mt][3]),
                          "r"(bf[nt][0]), "r"(bf[nt][1]));
                }
        }
        __syncthreads();
    }

    // epilogue: c0,c1 -> (row g, col t4*2 / +1); c2,c3 -> (row g+8)
#pragma unroll
    for (int mt = 0; mt < 2; mt++) {
        int r0 = rowBase + mB + mt * 16 + g;
        int r1 = r0 + 8;
        float s0 = 1.0f, s1 = 1.0f;
        if (scale) {
            if (r0 < M) s0 = scale[r0];
            if (r1 < M) s1 = scale[r1];
        }
#pragma unroll
        for (int nt = 0; nt < 8; nt++) {
            int c = colBase + nB + nt * 8 + t4 * 2;
            float bx = 0.f, by = 0.f;
            if (bias) { bx = bias[c]; by = bias[c + 1]; }
            if (r0 < M) {
                float2 v;
                v.x = acc[mt][nt][0] * s0 + bx * s0;
                v.y = acc[mt][nt][1] * s0 + by * s0;
                *reinterpret_cast<float2*>(&C[(size_t)r0 * HID + c]) = v;
            }
            if (r1 < M) {
                float2 v;
                v.x = acc[mt][nt][2] * s1 + bx * s1;
                v.y = acc[mt][nt][3] * s1 + by * s1;
                *reinterpret_cast<float2*>(&C[(size_t)r1 * HID + c]) = v;
            }
        }
    }
}

// ---------------- gather (float4): out[d,:] = relu(dinv[d]*(sum + self) + b) ----------------
__global__ void gather_kernel(const float* __restrict__ hp, float* __restrict__ out,
                              const int* __restrict__ row_ptr, const int* __restrict__ csr_src,
                              const float* __restrict__ dinv, const float* __restrict__ bias, int n) {
    int warp = (blockIdx.x * blockDim.x + threadIdx.x) >> 5;
    int lane = threadIdx.x & 31;
    if (warp >= n) return;
    int beg = row_ptr[warp];
    int end = row_ptr[warp + 1];

    float4 a0 = make_float4(0.f, 0.f, 0.f, 0.f);
    float4 a1 = make_float4(0.f, 0.f, 0.f, 0.f);

    for (int e = beg; e < end; e++) {
        int src = csr_src[e];
        const float4* row = reinterpret_cast<const float4*>(hp + (size_t)src * HID);
        float4 v0 = __ldg(&row[lane * 2]);
        float4 v1 = __ldg(&row[lane * 2 + 1]);
        a0.x += v0.x; a0.y += v0.y; a0.z += v0.z; a0.w += v0.w;
        a1.x += v1.x; a1.y += v1.y; a1.z += v1.z; a1.w += v1.w;
    }
    const float4* selfrow = reinterpret_cast<const float4*>(hp + (size_t)warp * HID);
    float4 s0 = selfrow[lane * 2];
    float4 s1 = selfrow[lane * 2 + 1];
    const float4* b4 = reinterpret_cast<const float4*>(bias);
    float4 b0 = b4[lane * 2];
    float4 b1 = b4[lane * 2 + 1];
    float dv = dinv[warp];

    float4 o0, o1;
    o0.x = fmaxf(dv * (a0.x + s0.x) + b0.x, 0.f);
    o0.y = fmaxf(dv * (a0.y + s0.y) + b0.y, 0.f);
    o0.z = fmaxf(dv * (a0.z + s0.z) + b0.z, 0.f);
    o0.w = fmaxf(dv * (a0.w + s0.w) + b0.w, 0.f);
    o1.x = fmaxf(dv * (a1.x + s1.x) + b1.x, 0.f);
    o1.y = fmaxf(dv * (a1.y + s1.y) + b1.y, 0.f);
    o1.z = fmaxf(dv * (a1.z + s1.z) + b1.z, 0.f);
    o1.w = fmaxf(dv * (a1.w + s1.w) + b1.w, 0.f);

    float4* outrow = reinterpret_cast<float4*>(out + (size_t)warp * HID);
    outrow[lane * 2] = o0;
    outrow[lane * 2 + 1] = o1;
}

// ---------------- pooling ----------------
__global__ void pool_mean_kernel(const float* __restrict__ h, const int* __restrict__ gstart,
                                 float* __restrict__ pooled) {
    int g = blockIdx.x;
    int t = threadIdx.x;
    int beg = gstart[g];
    int end = gstart[g + 1];
    float sum = 0.0f;
    for (int i = beg; i < end; i++) sum += h[(size_t)i * HID + t];
    float c = (float)(end - beg);
    pooled[g * HID + t] = sum / fmaxf(c, 1.0f);
}

__global__ void out_gemm_kernel(const float* __restrict__ pooled, const float* __restrict__ W,
                                const float* __restrict__ b, float* __restrict__ out) {
    int idx = blockIdx.x * blockDim.x + threadIdx.x;
    if (idx >= NGRAPH * NCLS) return;
    int g = idx >> 4;
    int c = idx & 15;
    float s = b[c];
#pragma unroll 8
    for (int k = 0; k < HID; k++) s += pooled[g * HID + k] * W[k * NCLS + c];
    out[idx] = s;
}

// ---------------- launch ----------------
extern "C" void kernel_launch(void* const* d_in, const int* in_sizes, int n_in,
                              void* d_out, int out_size) {
    const float* x     = (const float*)d_in[0];
    const void*  ei    = d_in[1];
    const void*  batch = d_in[2];
    const float* W_in  = (const float*)d_in[3];
    const float* b_in  = (const float*)d_in[4];
    const float* W1    = (const float*)d_in[5];
    const float* b1    = (const float*)d_in[6];
    const float* W2    = (const float*)d_in[7];
    const float* b2    = (const float*)d_in[8];
    const float* W_out = (const float*)d_in[9];
    const float* b_out = (const float*)d_in[10];

    const int N = in_sizes[0] / INDIM;
    const int E = in_sizes[1] / 2;

    float *bufA, *bufB, *dinv, *pool;
    int *indeg, *row_ptr, *cursor, *csr_src, *gcnt, *gstart, *localscan;
    cudaGetSymbolAddress((void**)&bufA, g_bufA);
    cudaGetSymbolAddress((void**)&bufB, g_bufB);
    cudaGetSymbolAddress((void**)&dinv, g_dinv);
    cudaGetSymbolAddress((void**)&pool, g_pool);
    cudaGetSymbolAddress((void**)&indeg, g_indeg);
    cudaGetSymbolAddress((void**)&row_ptr, g_row_ptr);
    cudaGetSymbolAddress((void**)&cursor, g_cursor);
    cudaGetSymbolAddress((void**)&csr_src, g_csr_src);
    cudaGetSymbolAddress((void**)&gcnt, g_gcnt);
    cudaGetSymbolAddress((void**)&gstart, g_gstart);
    cudaGetSymbolAddress((void**)&localscan, g_localscan);

    detect_dtype_kernel<<<1, 256>>>((const int*)ei, 4096);

    zero_int_kernel<<<(N + 255) / 256, 256>>>(indeg, N);
    zero_int_kernel<<<1, NGRAPH>>>(gcnt, NGRAPH);
    hist_dst_kernel<<<(E + 255) / 256, 256>>>(ei, E, indeg);
    hist_batch_kernel<<<(N + 255) / 256, 256>>>(batch, N, gcnt);

    const int nb = (N + 1023) / 1024;
    scan_local_kernel<<<nb, 1024>>>(indeg, localscan, N);
    scan_blocksums_kernel<<<1, 64>>>(nb);
    scan_finalize_kernel<<<(N + 255) / 256, 256>>>(indeg, localscan, row_ptr, cursor, N);
    dinv_kernel<<<(N + 255) / 256, 256>>>(indeg, dinv, N);
    fill_csr_kernel<<<(E + 255) / 256, 256>>>(ei, E, cursor, csr_src);
    scan_graphs_kernel<<<1, NGRAPH>>>(gcnt, gstart);

    dim3 ggrid(HID / BN, (N + BM - 1) / BM);

    tf32gemm_kernel<<<ggrid, 256>>>(x, W_in, bufA, N, INDIM, b_in, nullptr);

    tf32gemm_kernel<<<ggrid, 256>>>(bufA, W1, bufB, N, HID, nullptr, dinv);
    gather_kernel<<<(N * 32 + 255) / 256, 256>>>(bufB, bufA, row_ptr, csr_src, dinv, b1, N);

    tf32gemm_kernel<<<ggrid, 256>>>(bufA, W2, bufB, N, HID, nullptr, dinv);
    gather_kernel<<<(N * 32 + 255) / 256, 256>>>(bufB, bufA, row_ptr, csr_src, dinv, b2, N);

    pool_mean_kernel<<<NGRAPH, HID>>>(bufA, gstart, pool);
    out_gemm_kernel<<<(NGRAPH * NCLS + 255) / 256, 256>>>(pool, W_out, b_out, (float*)d_out);
}